// round 1
// baseline (speedup 1.0000x reference)
#include <cuda_runtime.h>

#define IN_SIZE 448
#define OUT_SIZE 224

__device__ __forceinline__ float sig10(float z) {
    // jax.nn.sigmoid(10*z); expf saturates to 0/inf cleanly for |z| large
    return 1.0f / (1.0f + expf(-10.0f * z));
}

__global__ void __launch_bounds__(OUT_SIZE) racnn_kernel(
    const float* __restrict__ images,   // [64, 3, 448, 448]
    const float* __restrict__ locs,     // [64, 3]
    float* __restrict__ out)            // [64, 3, 224, 224]
{
    const int jr = blockIdx.x;   // output row
    const int b  = blockIdx.y;   // batch
    const int jc = threadIdx.x;  // output col

    // ---- per-batch crop parameters (redundant per-thread, ~30 flops) ----
    float tx = locs[b * 3 + 0];
    float ty = locs[b * 3 + 1];
    float tl = locs[b * 3 + 2];

    tl = fmaxf(tl, 448.0f / 3.0f);
    // jnp.clip(x, lo, hi) == min(max(x, lo), hi)
    tx = fminf(fmaxf(tx, tl), (float)IN_SIZE - tl);
    ty = fminf(fmaxf(ty, tl), (float)IN_SIZE - tl);

    const float w_off = fmaxf(floorf(tx - tl), 0.0f);
    const float h_off = fmaxf(floorf(ty - tl), 0.0f);
    const float w_end = fminf(floorf(tx + tl), (float)IN_SIZE);
    const float h_end = fminf(floorf(ty + tl), (float)IN_SIZE);

    // ---- row mapping (src_r indexes dim-1 of img, masked by mrow) ----
    const float jrf = (float)jr;
    const float src_r = w_off + (jrf * (w_end - w_off - 1.0f)) / (float)(OUT_SIZE - 1);
    float r0 = floorf(src_r);
    r0 = fminf(fmaxf(r0, 0.0f), (float)(IN_SIZE - 1));
    const float wr = src_r - r0;
    const int r0i = (int)r0;
    const int r1i = min(r0i + 1, IN_SIZE - 1);

    const float mrow0 = sig10((float)r0i - w_off) - sig10((float)r0i - w_end);
    const float mrow1 = sig10((float)r1i - w_off) - sig10((float)r1i - w_end);

    // ---- col mapping ----
    const float jcf = (float)jc;
    const float src_c = h_off + (jcf * (h_end - h_off - 1.0f)) / (float)(OUT_SIZE - 1);
    float c0 = floorf(src_c);
    c0 = fminf(fmaxf(c0, 0.0f), (float)(IN_SIZE - 1));
    const float wc = src_c - c0;
    const int c0i = (int)c0;
    const int c1i = min(c0i + 1, IN_SIZE - 1);

    const float mcol0 = sig10((float)c0i - h_off) - sig10((float)c0i - h_end);
    const float mcol1 = sig10((float)c1i - h_off) - sig10((float)c1i - h_end);

    // ---- fused bilinear x attention-mask weights (channel-invariant) ----
    const float w00 = (1.0f - wr) * (1.0f - wc) * mrow0 * mcol0;
    const float w01 = (1.0f - wr) * wc          * mrow0 * mcol1;
    const float w10 = wr          * (1.0f - wc) * mrow1 * mcol0;
    const float w11 = wr          * wc          * mrow1 * mcol1;

    // ---- 3 channels: 4 taps + 1 store each ----
    const long long img_base = (long long)b * 3 * IN_SIZE * IN_SIZE;
    const long long out_base = (long long)b * 3 * OUT_SIZE * OUT_SIZE;

#pragma unroll
    for (int ch = 0; ch < 3; ch++) {
        const float* img = images + img_base + (long long)ch * IN_SIZE * IN_SIZE;
        const float* row0 = img + (long long)r0i * IN_SIZE;
        const float* row1 = img + (long long)r1i * IN_SIZE;

        const float x00 = __ldg(row0 + c0i);
        const float x01 = __ldg(row0 + c1i);
        const float x10 = __ldg(row1 + c0i);
        const float x11 = __ldg(row1 + c1i);

        const float v = w00 * x00 + w01 * x01 + w10 * x10 + w11 * x11;
        out[out_base + (long long)ch * OUT_SIZE * OUT_SIZE + (long long)jr * OUT_SIZE + jc] = v;
    }
}

extern "C" void kernel_launch(void* const* d_in, const int* in_sizes, int n_in,
                              void* d_out, int out_size) {
    const float* images = (const float*)d_in[0];
    const float* locs   = (const float*)d_in[1];
    float* out = (float*)d_out;

    dim3 grid(OUT_SIZE, 64);
    dim3 block(OUT_SIZE);
    racnn_kernel<<<grid, block>>>(images, locs, out);
}

// round 2
// speedup vs baseline: 1.6964x; 1.6964x over previous
#include <cuda_runtime.h>

#define IN_SIZE 448
#define OUT_SIZE 224
#define BATCH 64
#define ROWS_PER_BLK 2

// Scratch tables: {index0, index1, weight0, weight1} per (batch, j)
__device__ float4 g_rowtab[BATCH * OUT_SIZE];  // {r0*448, r1*448, a0, a1}
__device__ float4 g_coltab[BATCH * OUT_SIZE];  // {c0,     c1,     b0, b1}

__device__ __forceinline__ float sig10(float z) {
    return 1.0f / (1.0f + expf(-10.0f * z));
}

// ---------------------------------------------------------------------------
// Kernel A: precompute separable crop/resize tables. grid=64, block=224.
// ---------------------------------------------------------------------------
__global__ void __launch_bounds__(OUT_SIZE) precompute_tables(
    const float* __restrict__ locs)
{
    const int b = blockIdx.x;
    const int j = threadIdx.x;

    float tx = locs[b * 3 + 0];
    float ty = locs[b * 3 + 1];
    float tl = locs[b * 3 + 2];

    tl = fmaxf(tl, 448.0f / 3.0f);
    tx = fminf(fmaxf(tx, tl), (float)IN_SIZE - tl);
    ty = fminf(fmaxf(ty, tl), (float)IN_SIZE - tl);

    const float w_off = fmaxf(floorf(tx - tl), 0.0f);
    const float h_off = fmaxf(floorf(ty - tl), 0.0f);
    const float w_end = fminf(floorf(tx + tl), (float)IN_SIZE);
    const float h_end = fminf(floorf(ty + tl), (float)IN_SIZE);

    const float jf = (float)j;

    // ---- row entry (uses w_off/w_end) ----
    {
        const float src_r = w_off + (jf * (w_end - w_off - 1.0f)) / (float)(OUT_SIZE - 1);
        float r0 = fminf(fmaxf(floorf(src_r), 0.0f), (float)(IN_SIZE - 1));
        const float wr = src_r - r0;
        const int r0i = (int)r0;
        const int r1i = min(r0i + 1, IN_SIZE - 1);
        const float mrow0 = sig10((float)r0i - w_off) - sig10((float)r0i - w_end);
        const float mrow1 = sig10((float)r1i - w_off) - sig10((float)r1i - w_end);
        float4 e;
        e.x = __int_as_float(r0i * IN_SIZE);
        e.y = __int_as_float(r1i * IN_SIZE);
        e.z = (1.0f - wr) * mrow0;   // a0
        e.w = wr * mrow1;            // a1
        g_rowtab[b * OUT_SIZE + j] = e;
    }

    // ---- col entry (uses h_off/h_end) ----
    {
        const float src_c = h_off + (jf * (h_end - h_off - 1.0f)) / (float)(OUT_SIZE - 1);
        float c0 = fminf(fmaxf(floorf(src_c), 0.0f), (float)(IN_SIZE - 1));
        const float wc = src_c - c0;
        const int c0i = (int)c0;
        const int c1i = min(c0i + 1, IN_SIZE - 1);
        const float mcol0 = sig10((float)c0i - h_off) - sig10((float)c0i - h_end);
        const float mcol1 = sig10((float)c1i - h_off) - sig10((float)c1i - h_end);
        float4 e;
        e.x = __int_as_float(c0i);
        e.y = __int_as_float(c1i);
        e.z = (1.0f - wc) * mcol0;   // b0
        e.w = wc * mcol1;            // b1
        g_coltab[b * OUT_SIZE + j] = e;
    }
}

// ---------------------------------------------------------------------------
// Kernel B: gather + weighted sum. grid=(112, 64), block=224.
// Each block handles ROWS_PER_BLK output rows of one batch image.
// ---------------------------------------------------------------------------
__global__ void __launch_bounds__(OUT_SIZE) racnn_gather(
    const float* __restrict__ images,
    float* __restrict__ out)
{
    const int jr0 = blockIdx.x * ROWS_PER_BLK;
    const int b   = blockIdx.y;
    const int jc  = threadIdx.x;

    // col entry: coalesced 16B loads
    const float4 ce = g_coltab[b * OUT_SIZE + jc];
    const int   c0i = __float_as_int(ce.x);
    const int   c1i = __float_as_int(ce.y);
    const float b0  = ce.z;
    const float b1  = ce.w;

    // 32-bit element offsets (max image offset 38.5M < 2^31)
    const int img_base = b * 3 * IN_SIZE * IN_SIZE;
    const int out_base = b * 3 * OUT_SIZE * OUT_SIZE + jr0 * OUT_SIZE + jc;

#pragma unroll
    for (int r = 0; r < ROWS_PER_BLK; r++) {
        // row entry: warp-uniform broadcast load
        const float4 re = g_rowtab[b * OUT_SIZE + jr0 + r];
        const int   r0off = __float_as_int(re.x);
        const int   r1off = __float_as_int(re.y);
        const float a0 = re.z;
        const float a1 = re.w;

        const int p00 = img_base + r0off + c0i;
        const int p01 = img_base + r0off + c1i;
        const int p10 = img_base + r1off + c0i;
        const int p11 = img_base + r1off + c1i;

#pragma unroll
        for (int ch = 0; ch < 3; ch++) {
            const int cofs = ch * (IN_SIZE * IN_SIZE);
            const float x00 = __ldg(images + p00 + cofs);
            const float x01 = __ldg(images + p01 + cofs);
            const float x10 = __ldg(images + p10 + cofs);
            const float x11 = __ldg(images + p11 + cofs);

            const float top = fmaf(b1, x01, b0 * x00);
            const float bot = fmaf(b1, x11, b0 * x10);
            const float v   = fmaf(a1, bot, a0 * top);

            out[out_base + ch * (OUT_SIZE * OUT_SIZE) + r * OUT_SIZE] = v;
        }
    }
}

extern "C" void kernel_launch(void* const* d_in, const int* in_sizes, int n_in,
                              void* d_out, int out_size) {
    const float* images = (const float*)d_in[0];
    const float* locs   = (const float*)d_in[1];
    float* out = (float*)d_out;

    precompute_tables<<<BATCH, OUT_SIZE>>>(locs);

    dim3 grid(OUT_SIZE / ROWS_PER_BLK, BATCH);
    racnn_gather<<<grid, OUT_SIZE>>>(images, out);
}